// round 14
// baseline (speedup 1.0000x reference)
#include <cuda_runtime.h>

#define EPSV 1e-5f
#define RSQRT8 0.35355339059327373f

// scratch (allocation-free rule: device globals)
__device__ float g_q[4*512*64];
__device__ float g_k[4*512*64];
__device__ float g_v[4*512*64];

typedef unsigned long long ull;

__device__ __forceinline__ ull splat2(float x){
    ull r; unsigned u = __float_as_uint(x);
    asm("mov.b64 %0, {%1,%1};" : "=l"(r) : "r"(u));
    return r;
}
__device__ __forceinline__ void fma2a(ull& d, ull a, ull b){
    asm("fma.rn.f32x2 %0, %1, %2, %0;" : "+l"(d) : "l"(a), "l"(b));
}
__device__ __forceinline__ ull mul2(ull a, ull b){
    ull d; asm("mul.rn.f32x2 %0, %1, %2;" : "=l"(d) : "l"(a), "l"(b));
    return d;
}
__device__ __forceinline__ void add2a(ull& d, ull a){
    asm("add.rn.f32x2 %0, %0, %1;" : "+l"(d) : "l"(a));
}
__device__ __forceinline__ float2 unpack2(ull v){
    unsigned lo, hi;
    asm("mov.b64 {%0,%1}, %2;" : "=r"(lo), "=r"(hi) : "l"(v));
    return make_float2(__uint_as_float(lo), __uint_as_float(hi));
}
__device__ __forceinline__ float hsum2(ull v){
    float2 u = unpack2(v); return u.x + u.y;
}
__device__ __forceinline__ void cpa16(const void* sd, const void* g){
    unsigned s = (unsigned)__cvta_generic_to_shared(sd);
    asm volatile("cp.async.cg.shared.global [%0], [%1], 16;" :: "r"(s), "l"(g));
}
__device__ __forceinline__ unsigned tf32r(float x){
    unsigned r; asm("cvt.rna.tf32.f32 %0, %1;" : "=r"(r) : "f"(x)); return r;
}
__device__ __forceinline__ void mma8(float* d, unsigned a0, unsigned a1, unsigned a2, unsigned a3,
                                     unsigned b0, unsigned b1){
    asm("mma.sync.aligned.m16n8k8.row.col.f32.tf32.tf32.f32 "
        "{%0,%1,%2,%3},{%4,%5,%6,%7},{%8,%9},{%0,%1,%2,%3};"
        : "+f"(d[0]), "+f"(d[1]), "+f"(d[2]), "+f"(d[3])
        : "r"(a0), "r"(a1), "r"(a2), "r"(a3), "r"(b0), "r"(b1));
}

// ===================== Kernel 1: LN1 + QKV projection (4 rows/block) =====================
__global__ void __launch_bounds__(256)
qkv_kernel(const float* __restrict__ h, const float* __restrict__ Wh,
           const float* __restrict__ g1, const float* __restrict__ b1)
{
    __shared__ float hn[4][64];
    __shared__ float part[4][4];
    int t = threadIdx.x;
    int g = t >> 6, tl = t & 63;
    int row = blockIdx.x*4 + g;
    float x = h[row*64 + tl];
    float s = x, q = x*x;
    #pragma unroll
    for (int o = 16; o >= 1; o >>= 1){
        s += __shfl_xor_sync(0xffffffffu, s, o);
        q += __shfl_xor_sync(0xffffffffu, q, o);
    }
    if ((tl & 31) == 0){ part[g][tl>>5] = s; part[g][2 + (tl>>5)] = q; }
    __syncthreads();
    float mean = (part[g][0] + part[g][1]) * (1.f/64.f);
    float var  = (part[g][2] + part[g][3]) * (1.f/64.f) - mean*mean;
    float hv = (x - mean) * rsqrtf(var + EPSV) * g1[tl] + b1[tl];
    hn[g][tl] = hv;
    __syncthreads();
    float aq = 0.f, ak = 0.f, av = 0.f;
    #pragma unroll 8
    for (int i = 0; i < 64; i++){
        float z = hn[g][i];
        aq = fmaf(z, Wh[i*192 + tl],       aq);
        ak = fmaf(z, Wh[i*192 + 64 + tl],  ak);
        av = fmaf(z, Wh[i*192 + 128 + tl], av);
    }
    g_q[row*64 + tl] = aq;
    g_k[row*64 + tl] = ak;
    g_v[row*64 + tl] = av;
}

// ===================== Kernel 2: barrier-free warp pipelines, k-split for occupancy =====================
// 512 blocks x 256 threads (8 warps). Block owns 4 q-rows; warp w = (qrow = w>>1, k-half = w&1).
// Each warp streams ITS half of the k-range: 32 tiles of 8 k-rows, warp-private triple buffer,
// prefetch distance 2, __syncwarp-only main loop. 3 blocks/SM (65 KB smem, <=85 regs) -> ~24 warps/SM.
// Phase1: ew[8x16] = E[8x64]@We[64x16] via mma m16n8k8 (rows 8..15 dup, discarded);
//   B frags from we_frag (prepacked fragment order, LDS.128).
// Phase2: lane (h=lane&7, gg=lane>>3): k-rows {2gg,2gg+1} x head h; k/v via LDG.
// smem floats (16256 = 65024 B):
//   e_w 8x1632 (=13056) | ew_w 8x160 @13056 | we_frag 1024 @14336 | red 640 @15360 | y 256 @16000
// Post-loop overlays: z_s=smem+0 (256), hid_s=smem+256 (1024).
__global__ void __launch_bounds__(256, 3)
attn_kernel(const float* __restrict__ e, const float* __restrict__ We,
            const float* __restrict__ hin, const float* __restrict__ w1,
            const float* __restrict__ w2, const float* __restrict__ g2,
            const float* __restrict__ b2, float* __restrict__ out)
{
    extern __shared__ float smem[];

    const int t    = threadIdx.x;
    const int w    = t >> 5;
    const int lane = t & 31;
    const int h    = lane & 7;          // head
    const int gg   = lane >> 3;         // 0..3 -> k-rows 2gg, 2gg+1
    const int qr   = w >> 1;            // q-row within block (0..3)
    const int kh   = w & 1;             // k-half (0..1)
    const int bx   = blockIdx.x;
    const int b    = bx >> 7;           // 128 blocks per batch
    const int q0   = (bx & 127) << 2;   // 4 q rows per block
    const int qrow = q0 + qr;

    float* e_w     = smem + w*1632;        // [3][544]
    float* ew_w    = smem + 13056 + w*160; // [8][20]
    float* we_frag = smem + 14336;         // [8][32][4]
    float* red_s   = smem + 15360;         // [4][2][8][10]
    float* y_s     = smem + 16000;         // [256]
    float* z_s     = smem;                 // overlay, post-sync only
    float* hid_s   = smem + 256;           // overlay, post-sync only

    // ---- e copy addressing: 8 rows x 64 fl per tile; lane copies 4 x 16B ----
    const char* pe = (const char*)(e + (size_t)(b*512 + qrow)*32768 + (size_t)kh*16384) + lane*16;
    char* edBase = (char*)e_w + (lane>>4)*272 + (lane&15)*16;

    // ---- prologue: issue tiles 0,1 (2 groups in flight) ----
    #pragma unroll
    for (int x = 0; x < 2; x++){
        char* ed = edBase + x*2176;
        #pragma unroll
        for (int i = 0; i < 4; i++) cpa16(ed + i*544, pe + i*512);
        asm volatile("cp.async.commit_group;");
        pe += 2048;
    }

    // ---- prepack B fragments into we_frag (fragment order; rna tf32) ----
    {
        int s = t >> 5, ln = t & 31, kq = ln & 3, nq = ln >> 2;
        float4 bf;
        bf.x = __uint_as_float(tf32r(We[(s*8 + kq)*16 + nq]));
        bf.y = __uint_as_float(tf32r(We[(s*8 + kq)*16 + 8 + nq]));
        bf.z = __uint_as_float(tf32r(We[(s*8 + kq + 4)*16 + nq]));
        bf.w = __uint_as_float(tf32r(We[(s*8 + kq + 4)*16 + 8 + nq]));
        ((float4*)we_frag)[t] = bf;
    }

    // ---- q regs (1 row x head h) ----
    ulonglong2 qA, qB;
    {
        const ulonglong2* qp = (const ulonglong2*)(g_q + (size_t)(b*512 + qrow)*64 + 8*h);
        qA = qp[0]; qB = qp[1];
    }
    const char* pk = (const char*)(g_k + (size_t)(b*512)*64 + (size_t)kh*16384) + gg*512 + h*32;
    const char* pv = (const char*)(g_v + (size_t)(b*512)*64 + (size_t)kh*16384) + gg*512 + h*32;

    __syncthreads();   // we_frag visible to all warps

    float l = 0.f;
    ull acc[4] = {0ull, 0ull, 0ull, 0ull};

    const int r4 = lane >> 2, cq = lane & 3;
    int bufc = 0;      // consume buffer
    int ibc  = 2;      // issue buffer (tile+2)

    for (int tile = 0; tile < 32; tile++){
        if (tile < 31){ asm volatile("cp.async.wait_group 1;"); }
        else          { asm volatile("cp.async.wait_group 0;"); }
        __syncwarp();   // tile's buffer ready; all lanes past prior ew reads

        if (tile < 30){
            char* ed = edBase + ibc*2176;
            #pragma unroll
            for (int i = 0; i < 4; i++) cpa16(ed + i*544, pe + i*512);
            asm volatile("cp.async.commit_group;");
            pe += 2048;
            ibc = (ibc == 2) ? 0 : ibc + 1;
        }

        // ---- Phase 1: ew = E[8x64] @ We[64x16] (rows 8..15 duplicated garbage) ----
        {
            const float* eA = e_w + bufc*544 + r4*68 + cq;
            float d0[4], d1[4];
            d0[0]=d0[1]=d0[2]=d0[3]=0.f;
            d1[0]=d1[1]=d1[2]=d1[3]=0.f;
            #pragma unroll
            for (int s = 0; s < 8; s++){
                unsigned a0 = __float_as_uint(eA[s*8]);
                unsigned a2 = __float_as_uint(eA[s*8 + 4]);
                float4 bf = ((const float4*)we_frag)[s*32 + lane];
                mma8(d0, a0, a0, a2, a2, __float_as_uint(bf.x), __float_as_uint(bf.z));
                mma8(d1, a0, a0, a2, a2, __float_as_uint(bf.y), __float_as_uint(bf.w));
            }
            float* ewp = ew_w + r4*20 + 4*cq;
            *(float4*)ewp = make_float4(d0[0], d1[0], d0[1], d1[1]);  // {e1,e2} cols 2cq, 2cq+1
        }
        __syncwarp();

        // ---- Phase 2: k-rows 2gg, 2gg+1 x head h ----
        {
            ulonglong2 kA0 = *(const ulonglong2*)(pk);
            ulonglong2 kB0 = *(const ulonglong2*)(pk + 16);
            ulonglong2 kA1 = *(const ulonglong2*)(pk + 256);
            ulonglong2 kB1 = *(const ulonglong2*)(pk + 272);
            ulonglong2 vA0 = *(const ulonglong2*)(pv);
            ulonglong2 vB0 = *(const ulonglong2*)(pv + 16);
            ulonglong2 vA1 = *(const ulonglong2*)(pv + 256);
            ulonglong2 vB1 = *(const ulonglong2*)(pv + 272);
            const float* ewr = ew_w + gg*40 + 2*h;
            float2 ez0 = *(const float2*)(ewr);
            float2 ez1 = *(const float2*)(ewr + 20);

            ull s0 = mul2(qA.x, kA0.x); fma2a(s0, qA.y, kA0.y);
            fma2a(s0, qB.x, kB0.x);     fma2a(s0, qB.y, kB0.y);
            ull s1 = mul2(qA.x, kA1.x); fma2a(s1, qA.y, kA1.y);
            fma2a(s1, qB.x, kB1.x);     fma2a(s1, qB.y, kB1.y);
            float p0 = __expf(fmaf(hsum2(s0), RSQRT8, ez0.x));
            float p1 = __expf(fmaf(hsum2(s1), RSQRT8, ez1.x));
            l += p0 + p1;
            ull g0 = splat2(p0 * ez0.y);
            ull g1 = splat2(p1 * ez1.y);
            fma2a(acc[0], g0, vA0.x); fma2a(acc[1], g0, vA0.y);
            fma2a(acc[2], g0, vB0.x); fma2a(acc[3], g0, vB0.y);
            fma2a(acc[0], g1, vA1.x); fma2a(acc[1], g1, vA1.y);
            fma2a(acc[2], g1, vB1.x); fma2a(acc[3], g1, vB1.y);
        }
        pk += 2048; pv += 2048;
        bufc = (bufc == 2) ? 0 : bufc + 1;
    }

    // ---- reduce over gg (lanes xor 8, 16); lane (gg==0, h) holds head h partials ----
    #pragma unroll
    for (int off = 16; off >= 8; off >>= 1){
        l += __shfl_xor_sync(0xffffffffu, l, off);
        #pragma unroll
        for (int i = 0; i < 4; i++)
            add2a(acc[i], __shfl_xor_sync(0xffffffffu, acc[i], off));
    }
    if (gg == 0){
        float* p = red_s + ((qr*2 + kh)*8 + h)*10;
        #pragma unroll
        for (int d2 = 0; d2 < 4; d2++){
            float2 u = unpack2(acc[d2]);
            *(float2*)(p + 2*d2) = u;
        }
        p[8] = l;
    }
    __syncthreads();   // block barrier before epilogue

    // ---- y: sum the two k-half partials, divide by l ----
    {
        int q = t >> 6, d = t & 63;
        int hh = d >> 3, j = d & 7;
        const float* p0 = red_s + ((q*2 + 0)*8 + hh)*10;
        const float* p1 = red_s + ((q*2 + 1)*8 + hh)*10;
        float a  = p0[j] + p1[j];
        float ll = p0[8] + p1[8];
        y_s[t] = a * __fdividef(1.f, ll);
    }
    __syncthreads();

    // ---- LN2 over (y + h_in): warps 0..3 -> rows 0..3 (z_s overlays smem base) ----
    if (w < 4){
        const float* hrow = hin + (size_t)(b*512 + q0 + w) * 64;
        float x0 = y_s[w*64 + lane]      + hrow[lane];
        float x1 = y_s[w*64 + lane + 32] + hrow[lane + 32];
        float s = x0 + x1, sq = x0*x0 + x1*x1;
        #pragma unroll
        for (int o = 16; o >= 1; o >>= 1){
            s  += __shfl_xor_sync(0xffffffffu, s, o);
            sq += __shfl_xor_sync(0xffffffffu, sq, o);
        }
        float mean = s * (1.f/64.f);
        float var  = sq * (1.f/64.f) - mean*mean;
        float rs = rsqrtf(var + EPSV);
        z_s[w*64 + lane]      = (x0 - mean) * rs * g2[lane]      + b2[lane];
        z_s[w*64 + lane + 32] = (x1 - mean) * rs * g2[lane + 32] + b2[lane + 32];
    }
    __syncthreads();

    // ---- hidden = relu(z @ w1)  [4 x 256]: one column per thread ----
    {
        int col = t;
        float a0 = 0.f, a1 = 0.f, a2 = 0.f, a3 = 0.f;
        #pragma unroll 8
        for (int i = 0; i < 64; i++){
            float wvv = w1[i*256 + col];
            a0 = fmaf(z_s[i],       wvv, a0);
            a1 = fmaf(z_s[64 + i],  wvv, a1);
            a2 = fmaf(z_s[128 + i], wvv, a2);
            a3 = fmaf(z_s[192 + i], wvv, a3);
        }
        hid_s[col]       = fmaxf(a0, 0.f);
        hid_s[256 + col] = fmaxf(a1, 0.f);
        hid_s[512 + col] = fmaxf(a2, 0.f);
        hid_s[768 + col] = fmaxf(a3, 0.f);
    }
    __syncthreads();

    // ---- out = hidden @ w2 + y : one output element per thread ----
    {
        int d = t & 63, r = t >> 6;
        float a = 0.f;
        #pragma unroll 8
        for (int j = 0; j < 256; j++)
            a = fmaf(hid_s[r*256 + j], w2[j*64 + d], a);
        out[((size_t)(b*512 + q0 + r)) * 64 + d] = a + y_s[r*64 + d];
    }
}

extern "C" void kernel_launch(void* const* d_in, const int* in_sizes, int n_in,
                              void* d_out, int out_size)
{
    const float* h  = (const float*)d_in[0];
    const float* e  = (const float*)d_in[1];
    const float* Wh = (const float*)d_in[2];
    const float* We = (const float*)d_in[3];
    const float* w1 = (const float*)d_in[4];
    const float* w2 = (const float*)d_in[5];
    const float* g1 = (const float*)d_in[6];
    const float* b1 = (const float*)d_in[7];
    const float* g2 = (const float*)d_in[8];
    const float* b2 = (const float*)d_in[9];
    float* out = (float*)d_out;

    cudaFuncSetAttribute(attn_kernel, cudaFuncAttributeMaxDynamicSharedMemorySize, 65024);

    qkv_kernel<<<512, 256>>>(h, Wh, g1, b1);
    attn_kernel<<<512, 256, 65024>>>(e, We, h, w1, w2, g2, b2, out);
}

// round 15
// speedup vs baseline: 1.6055x; 1.6055x over previous
#include <cuda_runtime.h>

#define EPSV 1e-5f
#define RSQRT8 0.35355339059327373f

// scratch (allocation-free rule: device globals)
__device__ float g_q[4*512*64];
__device__ float g_k[4*512*64];
__device__ float g_v[4*512*64];

typedef unsigned long long ull;

__device__ __forceinline__ ull splat2(float x){
    ull r; unsigned u = __float_as_uint(x);
    asm("mov.b64 %0, {%1,%1};" : "=l"(r) : "r"(u));
    return r;
}
__device__ __forceinline__ void fma2a(ull& d, ull a, ull b){
    asm("fma.rn.f32x2 %0, %1, %2, %0;" : "+l"(d) : "l"(a), "l"(b));
}
__device__ __forceinline__ ull mul2(ull a, ull b){
    ull d; asm("mul.rn.f32x2 %0, %1, %2;" : "=l"(d) : "l"(a), "l"(b));
    return d;
}
__device__ __forceinline__ void add2a(ull& d, ull a){
    asm("add.rn.f32x2 %0, %0, %1;" : "+l"(d) : "l"(a));
}
__device__ __forceinline__ float2 unpack2(ull v){
    unsigned lo, hi;
    asm("mov.b64 {%0,%1}, %2;" : "=r"(lo), "=r"(hi) : "l"(v));
    return make_float2(__uint_as_float(lo), __uint_as_float(hi));
}
__device__ __forceinline__ float hsum2(ull v){
    float2 u = unpack2(v); return u.x + u.y;
}
__device__ __forceinline__ void cpa16(const void* sd, const void* g){
    unsigned s = (unsigned)__cvta_generic_to_shared(sd);
    asm volatile("cp.async.cg.shared.global [%0], [%1], 16;" :: "r"(s), "l"(g));
}
__device__ __forceinline__ unsigned tf32r(float x){
    unsigned r; asm("cvt.rna.tf32.f32 %0, %1;" : "=r"(r) : "f"(x)); return r;
}
__device__ __forceinline__ void mma8(float* d, unsigned a0, unsigned a1, unsigned a2, unsigned a3,
                                     unsigned b0, unsigned b1){
    asm("mma.sync.aligned.m16n8k8.row.col.f32.tf32.tf32.f32 "
        "{%0,%1,%2,%3},{%4,%5,%6,%7},{%8,%9},{%0,%1,%2,%3};"
        : "+f"(d[0]), "+f"(d[1]), "+f"(d[2]), "+f"(d[3])
        : "r"(a0), "r"(a1), "r"(a2), "r"(a3), "r"(b0), "r"(b1));
}

// ===================== Kernel 1: LN1 + QKV projection (4 rows/block) =====================
__global__ void __launch_bounds__(256)
qkv_kernel(const float* __restrict__ h, const float* __restrict__ Wh,
           const float* __restrict__ g1, const float* __restrict__ b1)
{
    __shared__ float hn[4][64];
    __shared__ float part[4][4];
    int t = threadIdx.x;
    int g = t >> 6, tl = t & 63;
    int row = blockIdx.x*4 + g;
    float x = h[row*64 + tl];
    float s = x, q = x*x;
    #pragma unroll
    for (int o = 16; o >= 1; o >>= 1){
        s += __shfl_xor_sync(0xffffffffu, s, o);
        q += __shfl_xor_sync(0xffffffffu, q, o);
    }
    if ((tl & 31) == 0){ part[g][tl>>5] = s; part[g][2 + (tl>>5)] = q; }
    __syncthreads();
    float mean = (part[g][0] + part[g][1]) * (1.f/64.f);
    float var  = (part[g][2] + part[g][3]) * (1.f/64.f) - mean*mean;
    float hv = (x - mean) * rsqrtf(var + EPSV) * g1[tl] + b1[tl];
    hn[g][tl] = hv;
    __syncthreads();
    float aq = 0.f, ak = 0.f, av = 0.f;
    #pragma unroll 8
    for (int i = 0; i < 64; i++){
        float z = hn[g][i];
        aq = fmaf(z, Wh[i*192 + tl],       aq);
        ak = fmaf(z, Wh[i*192 + 64 + tl],  ak);
        av = fmaf(z, Wh[i*192 + 128 + tl], av);
    }
    g_q[row*64 + tl] = aq;
    g_k[row*64 + tl] = ak;
    g_v[row*64 + tl] = av;
}

// ===================== Kernel 2: barrier-free warp pipelines (R11) + coalesced k/v =====================
// 256 threads = 8 warps; warp w owns q-row q0+w ALONE. 256 blocks (single wave), 2 blocks/SM.
// Main loop __syncwarp-only; 16 k-rows/tile, 32 tiles, warp-private double buffer (dist 1).
// Phase1: ew[16x16] = E[16x64]@We[64x16] via mma m16n8k8 (all rows valid; B rna in regs).
// Phase2 (COALESCED): lane = (rowpar=lane>>4, hh=(lane>>1)&7, half=lane&1);
//   per i (8 iters): lane loads the 16B k and v chunk at [tile + i*512 + lane*16] -> every
//   LDG.128 is fully coalesced (4 wavefronts). Half-head dot + shfl_xor(1) to combine halves.
// smem floats: e_w per warp [2][1088] at w*2176 (17408) | ew_w per warp 16x20 at 17408+w*320
//   (2560) | y_s at 19968 (512). Post-loop overlays: z_s=smem+0, hid_s=smem+1024.
//   Total 20480 fl = 81920 B -> 2 blocks/SM.
__global__ void __launch_bounds__(256, 2)
attn_kernel(const float* __restrict__ e, const float* __restrict__ We,
            const float* __restrict__ hin, const float* __restrict__ w1,
            const float* __restrict__ w2, const float* __restrict__ g2,
            const float* __restrict__ b2, float* __restrict__ out)
{
    extern __shared__ float smem[];

    const int t    = threadIdx.x;
    const int w    = t >> 5;
    const int lane = t & 31;
    const int hh     = (lane >> 1) & 7;  // head
    const int half   = lane & 1;         // 16B half of the head's 32B
    const int rowpar = lane >> 4;        // row parity within 2-row group
    const int bx   = blockIdx.x;
    const int b    = bx >> 6;           // 64 blocks per batch
    const int q0   = (bx & 63) << 3;    // 8 q rows per block
    const int qrow = q0 + w;

    float* e_w   = smem + w*2176;        // [2][1088]
    float* ew_w  = smem + 17408 + w*320; // [16][20]
    float* y_s   = smem + 19968;         // [512]
    float* z_s   = smem;                 // overlay, post-sync only
    float* hid_s = smem + 1024;          // overlay, post-sync only

    // ---- per-lane copy addressing (warp-private e tile: 16 rows x 64 floats) ----
    const int crow = lane >> 4;
    const int cch  = lane & 15;
    const char* pe = (const char*)(e + (size_t)(b*512 + qrow)*32768) + crow*256 + cch*16;
    char* ed0 = (char*)e_w + crow*272 + cch*16;

    // ---- issue tile 0 ----
    #pragma unroll
    for (int i = 0; i < 8; i++) cpa16(ed0 + i*544, pe + i*512);
    asm volatile("cp.async.commit_group;");
    pe += 4096;

    // ---- persistent B fragments (rna tf32) + q half-head regs ----
    unsigned b0f[16], b1f[16];
    {
        const int kq = lane & 3, nq = lane >> 2;
        #pragma unroll
        for (int s = 0; s < 8; s++){
            #pragma unroll
            for (int n = 0; n < 2; n++){
                b0f[s*2+n] = tf32r(We[(s*8 + kq)*16 + n*8 + nq]);
                b1f[s*2+n] = tf32r(We[(s*8 + kq + 4)*16 + n*8 + nq]);
            }
        }
    }
    ull qh0, qh1;
    {
        const ull* qp = (const ull*)(g_q + (size_t)(b*512 + qrow)*64 + hh*8 + half*4);
        qh0 = qp[0]; qh1 = qp[1];
    }
    // coalesced k/v stream pointers: lane*16 within contiguous 512B (2-row) groups
    const char* pk = (const char*)(g_k + (size_t)(b*512)*64) + lane*16;
    const char* pv = (const char*)(g_v + (size_t)(b*512)*64) + lane*16;

    float l = 0.f;
    ull acc0 = 0ull, acc1 = 0ull;       // half-head output accumulator (4 floats)

    const int r4 = lane >> 2, cq = lane & 3;
    const int ew_rd = 2*hh;

    for (int tile = 0; tile < 32; tile++){
        const int buf = tile & 1;
        if (tile < 31){
            char* ed = (char*)(e_w + (buf^1)*1088) + crow*272 + cch*16;
            #pragma unroll
            for (int i = 0; i < 8; i++) cpa16(ed + i*544, pe + i*512);
            asm volatile("cp.async.commit_group;");
            pe += 4096;
            asm volatile("cp.async.wait_group 1;");
        } else {
            asm volatile("cp.async.wait_group 0;");
        }
        __syncwarp();

        // ---- Phase 1: ew = E[16x64] @ We[64x16] ----
        {
            const float* eA = e_w + buf*1088 + r4*68 + cq;
            float d0[4] = {0.f,0.f,0.f,0.f};
            float d1[4] = {0.f,0.f,0.f,0.f};
            #pragma unroll
            for (int s = 0; s < 8; s++){
                unsigned a0 = __float_as_uint(eA[s*8]);
                unsigned a2 = __float_as_uint(eA[s*8 + 4]);
                unsigned a1 = __float_as_uint(eA[544 + s*8]);
                unsigned a3 = __float_as_uint(eA[544 + s*8 + 4]);
                mma8(d0, a0, a1, a2, a3, b0f[s*2],   b1f[s*2]);
                mma8(d1, a0, a1, a2, a3, b0f[s*2+1], b1f[s*2+1]);
            }
            float* ewp = ew_w + r4*20 + 4*cq;
            *(float4*)ewp         = make_float4(d0[0], d1[0], d0[1], d1[1]);  // {e1,e2} cols 2cq, 2cq+1
            *(float4*)(ewp + 160) = make_float4(d0[2], d1[2], d0[3], d1[3]);  // rows +8
        }
        __syncwarp();

        // ---- Phase 2: coalesced k/v; lane handles (row 2i+rowpar, head hh, half) ----
        #pragma unroll
        for (int i = 0; i < 8; i++){
            ulonglong2 kc = *(const ulonglong2*)(pk + i*512);
            ulonglong2 vc = *(const ulonglong2*)(pv + i*512);
            float2 ez = *(const float2*)(ew_w + (2*i + rowpar)*20 + ew_rd);
            ull s2 = mul2(qh0, kc.x);
            fma2a(s2, qh1, kc.y);
            float sh = hsum2(s2);
            float sfull = sh + __shfl_xor_sync(0xffffffffu, sh, 1);
            float p = __expf(fmaf(sfull, RSQRT8, ez.x));
            l += p;
            ull gv = splat2(p * ez.y);
            fma2a(acc0, gv, vc.x);
            fma2a(acc1, gv, vc.y);
        }
        pk += 4096; pv += 4096;
        __syncwarp();
    }

    // ---- reduce over rowpar (xor 16); every lane then holds full l, half-head acc ----
    l += __shfl_xor_sync(0xffffffffu, l, 16);
    add2a(acc0, __shfl_xor_sync(0xffffffffu, acc0, 16));
    add2a(acc1, __shfl_xor_sync(0xffffffffu, acc1, 16));

    if (rowpar == 0){
        float inv = __fdividef(1.f, l);
        float2 u0 = unpack2(acc0);
        float2 u1 = unpack2(acc1);
        float* yp = y_s + w*64 + hh*8 + half*4;
        yp[0] = u0.x * inv;
        yp[1] = u0.y * inv;
        yp[2] = u1.x * inv;
        yp[3] = u1.y * inv;
    }
    __syncthreads();   // the ONLY block barrier before the epilogue

    // ---- LN2 over (y + h_in): warp w -> row w ----
    {
        const float* hrow = hin + (size_t)(b*512 + q0 + w) * 64;
        float x0 = y_s[w*64 + lane]      + hrow[lane];
        float x1 = y_s[w*64 + lane + 32] + hrow[lane + 32];
        float s = x0 + x1, sq = x0*x0 + x1*x1;
        #pragma unroll
        for (int o = 16; o >= 1; o >>= 1){
            s  += __shfl_xor_sync(0xffffffffu, s, o);
            sq += __shfl_xor_sync(0xffffffffu, sq, o);
        }
        float mean = s * (1.f/64.f);
        float var  = sq * (1.f/64.f) - mean*mean;
        float rs = rsqrtf(var + EPSV);
        z_s[w*64 + lane]      = (x0 - mean) * rs * g2[lane]      + b2[lane];
        z_s[w*64 + lane + 32] = (x1 - mean) * rs * g2[lane + 32] + b2[lane + 32];
    }
    __syncthreads();

    // ---- hidden = relu(z @ w1)  [8 x 256]: one column per thread ----
    {
        int col = t;
        float a[8];
        #pragma unroll
        for (int r = 0; r < 8; r++) a[r] = 0.f;
        #pragma unroll 8
        for (int i = 0; i < 64; i++){
            float wvv = w1[i*256 + col];
            #pragma unroll
            for (int r = 0; r < 8; r++)
                a[r] = fmaf(z_s[r*64 + i], wvv, a[r]);
        }
        #pragma unroll
        for (int r = 0; r < 8; r++)
            hid_s[r*256 + col] = fmaxf(a[r], 0.f);
    }
    __syncthreads();

    // ---- out = hidden @ w2 + y : two output elements per thread ----
    {
        int d = t & 63, r = t >> 6;   // rows r and r+4
        float a0 = 0.f, a1 = 0.f;
        #pragma unroll 8
        for (int j = 0; j < 256; j++){
            float wvv = w2[j*64 + d];
            a0 = fmaf(hid_s[r*256 + j],     wvv, a0);
            a1 = fmaf(hid_s[(r+4)*256 + j], wvv, a1);
        }
        out[((size_t)(b*512 + q0 + r)) * 64 + d]     = a0 + y_s[r*64 + d];
        out[((size_t)(b*512 + q0 + r + 4)) * 64 + d] = a1 + y_s[(r+4)*64 + d];
    }
}

extern "C" void kernel_launch(void* const* d_in, const int* in_sizes, int n_in,
                              void* d_out, int out_size)
{
    const float* h  = (const float*)d_in[0];
    const float* e  = (const float*)d_in[1];
    const float* Wh = (const float*)d_in[2];
    const float* We = (const float*)d_in[3];
    const float* w1 = (const float*)d_in[4];
    const float* w2 = (const float*)d_in[5];
    const float* g1 = (const float*)d_in[6];
    const float* b1 = (const float*)d_in[7];
    const float* g2 = (const float*)d_in[8];
    const float* b2 = (const float*)d_in[9];
    float* out = (float*)d_out;

    cudaFuncSetAttribute(attn_kernel, cudaFuncAttributeMaxDynamicSharedMemorySize, 81920);

    qkv_kernel<<<512, 256>>>(h, Wh, g1, b1);
    attn_kernel<<<256, 256, 81920>>>(e, We, h, w1, w2, g2, b2, out);
}